// round 1
// baseline (speedup 1.0000x reference)
#include <cuda_runtime.h>

#define NN 65536
#define EE 524288
#define BB 1024
#define FEATN 64
#define NCLS 5
#define EN (EE + NN)

// ---------------- scratch (device globals; no allocs allowed) ----------------
__device__ float d_u[256];
__device__ float d_v[256];
__device__ float d_vb1[256];
__device__ float d_p[4], d_q[4], d_r[4], d_t[4];
__device__ __align__(16) float d_W2e[256 * 68];     // cols 0..63 = W2, 64 = W2@a2_src, 65 = W2@a2_dst
__device__ __align__(16) float4 d_S0[NN];
__device__ __align__(16) float4 d_S1[NN];
__device__ __align__(16) float d_g[NN * 64];        // g = h1 @ W2
__device__ float d_a2s[NN];
__device__ float d_a2d[NN];
__device__ float d_den2[NN];
__device__ __align__(16) float d_out2[NN * 64];     // gat2 numerator, then h2 in place
__device__ __align__(16) float d_pool[BB * 64];
__device__ int d_cnt[BB];
__device__ float d_fa[64];

// ---------------- zero scratch (fresh every replay) ----------------
__global__ void zero_k() {
    int i0 = blockIdx.x * blockDim.x + threadIdx.x;
    int stride = gridDim.x * blockDim.x;
    for (int i = i0; i < NN * 64; i += stride) d_out2[i] = 0.f;
    float* s0 = (float*)d_S0;
    float* s1 = (float*)d_S1;
    for (int i = i0; i < NN * 4; i += stride) { s0[i] = 0.f; s1[i] = 0.f; }
    for (int i = i0; i < NN; i += stride) d_den2[i] = 0.f;
    for (int i = i0; i < BB * 64; i += stride) d_pool[i] = 0.f;
    for (int i = i0; i < BB; i += stride) d_cnt[i] = 0;
    if (i0 < 64) d_fa[i0] = 0.f;
}

// ---------------- precompute rank-1 constants + extended W2 ----------------
__global__ void prep_k(const float* __restrict__ Win, const float* __restrict__ bin,
                       const float* __restrict__ W1, const float* __restrict__ a1s,
                       const float* __restrict__ a1d, const float* __restrict__ b1,
                       const float* __restrict__ W2, const float* __restrict__ a2sv,
                       const float* __restrict__ a2dv) {
    int j = threadIdx.x;  // 0..255
    float u = 0.f, v = 0.f;
    for (int k = 0; k < 64; k++) {
        float w1 = W1[k * 256 + j];
        u += Win[k] * w1;
        v += bin[k] * w1;
    }
    d_u[j] = u;
    d_v[j] = v;
    d_vb1[j] = v + b1[j];
    // row j of extended W2 (k index = j)
    float as = 0.f, ad = 0.f;
    for (int c = 0; c < 64; c++) {
        float w2 = W2[j * 64 + c];
        d_W2e[j * 68 + c] = w2;
        as += w2 * a2sv[c];
        ad += w2 * a2dv[c];
    }
    d_W2e[j * 68 + 64] = as;
    d_W2e[j * 68 + 65] = ad;
    d_W2e[j * 68 + 66] = 0.f;
    d_W2e[j * 68 + 67] = 0.f;
    __syncthreads();
    if (j < 4) {
        float p = 0.f, q = 0.f, r = 0.f, t = 0.f;
        for (int c = 0; c < 64; c++) {
            int idx = j * 64 + c;
            p += d_u[idx] * a1s[idx];
            q += d_v[idx] * a1s[idx];
            r += d_u[idx] * a1d[idx];
            t += d_v[idx] * a1d[idx];
        }
        d_p[j] = p; d_q[j] = q; d_r[j] = r; d_t[j] = t;
    }
}

// ---------------- GAT-1 edge pass: accumulate S0 (denominator) and S1 (Σ ex·x_s) ----------------
__global__ void gat1_k(const int* __restrict__ ei, const float* __restrict__ x) {
    int idx = blockIdx.x * 256 + threadIdx.x;
    if (idx >= EN) return;
    int s, d;
    if (idx < EE) { s = ei[idx]; d = ei[EE + idx]; }
    else          { s = idx - EE; d = s; }
    float xs = __ldg(&x[s]);
    float xd = __ldg(&x[d]);
    float ex[4];
#pragma unroll
    for (int h = 0; h < 4; h++) {
        float e = xs * d_p[h] + d_q[h] + xd * d_r[h] + d_t[h];
        e = (e > 0.f) ? e : 0.2f * e;
        ex[h] = expf(e);
    }
    atomicAdd(&d_S0[d], make_float4(ex[0], ex[1], ex[2], ex[3]));
    atomicAdd(&d_S1[d], make_float4(ex[0] * xs, ex[1] * xs, ex[2] * xs, ex[3] * xs));
}

// ---------------- fused h1 construction + GEMM [N,256]x[256,66] ----------------
// h1[n, h*64+c] = relu( (S1/S0)[n,h] * u[h*64+c] + (v+b1)[h*64+c] )
// outputs: g[n,0..63], a2s[n] (col 64), a2d[n] (col 65)
__global__ void gemm_k() {
    __shared__ __align__(16) float W2s[128 * 68];
    __shared__ float us[256], vbs[256];
    int tid = threadIdx.x;                 // 256
    int row = blockIdx.x * 64 + (tid >> 2);
    int jg = tid & 3;
    us[tid] = d_u[tid];
    vbs[tid] = d_vb1[tid];
    float4 s0 = d_S0[row], s1 = d_S1[row];
    float wh[4] = { s1.x / s0.x, s1.y / s0.y, s1.z / s0.z, s1.w / s0.w };
    float4 acc[5];
#pragma unroll
    for (int i = 0; i < 5; i++) acc[i] = make_float4(0.f, 0.f, 0.f, 0.f);
    bool last = (jg == 3);
#pragma unroll
    for (int kk = 0; kk < 256; kk += 128) {
        __syncthreads();
        {
            const float4* src = (const float4*)&d_W2e[kk * 68];
            float4* dst = (float4*)W2s;
            for (int i = tid; i < (128 * 68) / 4; i += 256) dst[i] = src[i];
        }
        __syncthreads();
#pragma unroll
        for (int hh = 0; hh < 2; hh++) {
            float whc = wh[(kk >> 6) + hh];     // compile-time index (kk, hh unrolled)
#pragma unroll 4
            for (int k2 = 0; k2 < 64; k2++) {
                int kg = kk + hh * 64 + k2;
                int k = hh * 64 + k2;
                float a = fmaxf(whc * us[kg] + vbs[kg], 0.f);
                const float* wr = &W2s[k * 68 + (jg << 4)];
#pragma unroll
                for (int i = 0; i < 4; i++) {
                    float4 wv = *(const float4*)&wr[i * 4];
                    acc[i].x += a * wv.x; acc[i].y += a * wv.y;
                    acc[i].z += a * wv.z; acc[i].w += a * wv.w;
                }
                if (last) {
                    float4 wv = *(const float4*)&wr[16];
                    acc[4].x += a * wv.x;
                    acc[4].y += a * wv.y;
                }
            }
        }
    }
#pragma unroll
    for (int i = 0; i < 4; i++)
        *(float4*)&d_g[row * 64 + (jg << 4) + (i << 2)] = acc[i];
    if (last) { d_a2s[row] = acc[4].x; d_a2d[row] = acc[4].y; }
}

// ---------------- GAT-2 edge pass: warp per edge, float2 lanes ----------------
__global__ void gat2_k(const int* __restrict__ ei) {
    int gid = blockIdx.x * 256 + threadIdx.x;
    int e = gid >> 5;
    int lane = gid & 31;
    if (e >= EN) return;
    int s, d;
    if (e < EE) { s = ei[e]; d = ei[EE + e]; }
    else        { s = e - EE; d = s; }
    float el = d_a2s[s] + d_a2d[d];
    el = (el > 0.f) ? el : 0.2f * el;
    float ex = expf(el);
    float2 gv = *(const float2*)&d_g[s * 64 + lane * 2];
    atomicAdd((float2*)&d_out2[d * 64 + lane * 2], make_float2(ex * gv.x, ex * gv.y));
    if (lane == 0) atomicAdd(&d_den2[d], ex);
}

// ---------------- h2 = relu(out2/den + b2), pool per graph ----------------
__global__ void hpool_k(const int* __restrict__ batch, const float* __restrict__ b2) {
    int gid = blockIdx.x * 256 + threadIdx.x;
    int n = gid >> 5;
    int lane = gid & 31;
    float inv = 1.f / d_den2[n];
    float2 o = *(float2*)&d_out2[n * 64 + lane * 2];
    float2 bb = *(const float2*)&b2[lane * 2];
    float h0 = fmaxf(o.x * inv + bb.x, 0.f);
    float h1 = fmaxf(o.y * inv + bb.y, 0.f);
    *(float2*)&d_out2[n * 64 + lane * 2] = make_float2(h0, h1);
    int bg = batch[n];
    atomicAdd((float2*)&d_pool[bg * 64 + lane * 2], make_float2(h0, h1));
    if (lane == 0) atomicAdd(&d_cnt[bg], 1);
}

// ---------------- feature attention: per-node 64x64 matvec + sigmoid ----------------
__global__ void att_k(const float* __restrict__ faW1, const float* __restrict__ fab1,
                      const float* __restrict__ faW2, const float* __restrict__ fab2,
                      const int* __restrict__ batch) {
    __shared__ __align__(16) float W1s[64 * 64];
    __shared__ __align__(16) float b1s[64];
    __shared__ __align__(16) float w2s[64];
    __shared__ float fas[64];
    int tid = threadIdx.x;  // 128
    for (int i = tid; i < 4096; i += 128) W1s[i] = faW1[i];
    if (tid < 64) { b1s[tid] = fab1[tid]; w2s[tid] = faW2[tid]; fas[tid] = 0.f; }
    __syncthreads();
    int n = blockIdx.x * 128 + tid;
    float hrow[64];
#pragma unroll
    for (int i = 0; i < 16; i++) {
        float4 v = *(const float4*)&d_out2[n * 64 + i * 4];
        hrow[i * 4] = v.x; hrow[i * 4 + 1] = v.y;
        hrow[i * 4 + 2] = v.z; hrow[i * 4 + 3] = v.w;
    }
    float res = fab2[0];
#pragma unroll
    for (int tc = 0; tc < 4; tc++) {
        float4 acc[4];
#pragma unroll
        for (int i = 0; i < 4; i++) acc[i] = *(const float4*)&b1s[tc * 16 + i * 4];
#pragma unroll
        for (int c = 0; c < 64; c++) {
            float hc = hrow[c];
#pragma unroll
            for (int i = 0; i < 4; i++) {
                float4 wv = *(const float4*)&W1s[c * 64 + tc * 16 + i * 4];
                acc[i].x += hc * wv.x; acc[i].y += hc * wv.y;
                acc[i].z += hc * wv.z; acc[i].w += hc * wv.w;
            }
        }
#pragma unroll
        for (int i = 0; i < 4; i++) {
            float4 wv2 = *(const float4*)&w2s[tc * 16 + i * 4];
            res += fmaxf(acc[i].x, 0.f) * wv2.x + fmaxf(acc[i].y, 0.f) * wv2.y +
                   fmaxf(acc[i].z, 0.f) * wv2.z + fmaxf(acc[i].w, 0.f) * wv2.w;
        }
    }
    float att = 1.f / (1.f + expf(-res));
    int f = n - batch[n] * FEATN;
    atomicAdd(&fas[f], att);
    __syncthreads();
    if (tid < 64) atomicAdd(&d_fa[tid], fas[tid]);
}

// ---------------- classifier + final_attention ----------------
__global__ void fin_k(const float* __restrict__ clsW, const float* __restrict__ clsb,
                      float* __restrict__ out) {
    if (blockIdx.x < 4) {
        int b = blockIdx.x * 256 + threadIdx.x;
        float inv = 1.f / fmaxf((float)d_cnt[b], 1.f);
        float p[64];
#pragma unroll
        for (int i = 0; i < 16; i++) {
            float4 v = *(const float4*)&d_pool[b * 64 + i * 4];
            p[i * 4] = v.x * inv; p[i * 4 + 1] = v.y * inv;
            p[i * 4 + 2] = v.z * inv; p[i * 4 + 3] = v.w * inv;
        }
#pragma unroll
        for (int j = 0; j < NCLS; j++) {
            float o = clsb[j];
#pragma unroll
            for (int c = 0; c < 64; c++) o += p[c] * clsW[c * NCLS + j];
            out[b * NCLS + j] = o;
        }
    } else {
        int f = threadIdx.x;
        if (f < 64) out[BB * NCLS + f] = d_fa[f] * (1.f / (float)BB);
    }
}

extern "C" void kernel_launch(void* const* d_in, const int* in_sizes, int n_in,
                              void* d_out, int out_size) {
    const float* x    = (const float*)d_in[0];
    const int*   ei   = (const int*)d_in[1];
    const int*   bat  = (const int*)d_in[2];
    const float* Win  = (const float*)d_in[3];
    const float* bin  = (const float*)d_in[4];
    const float* W1   = (const float*)d_in[5];
    const float* a1s  = (const float*)d_in[6];
    const float* a1d  = (const float*)d_in[7];
    const float* b1   = (const float*)d_in[8];
    const float* W2   = (const float*)d_in[9];
    const float* a2s  = (const float*)d_in[10];
    const float* a2d  = (const float*)d_in[11];
    const float* b2   = (const float*)d_in[12];
    const float* faW1 = (const float*)d_in[13];
    const float* fab1 = (const float*)d_in[14];
    const float* faW2 = (const float*)d_in[15];
    const float* fab2 = (const float*)d_in[16];
    const float* clsW = (const float*)d_in[17];
    const float* clsb = (const float*)d_in[18];
    float* out = (float*)d_out;

    zero_k<<<1024, 256>>>();
    prep_k<<<1, 256>>>(Win, bin, W1, a1s, a1d, b1, W2, a2s, a2d);
    gat1_k<<<(EN + 255) / 256, 256>>>(ei, x);
    gemm_k<<<NN / 64, 256>>>();
    gat2_k<<<EN / 8, 256>>>(ei);
    hpool_k<<<NN / 8, 256>>>(bat, b2);
    att_k<<<NN / 128, 128>>>(faW1, fab1, faW2, fab2, bat);
    fin_k<<<5, 256>>>(clsW, clsb, out);
}

// round 2
// speedup vs baseline: 2.4191x; 2.4191x over previous
#include <cuda_runtime.h>

#define NN 65536
#define EE 524288
#define BB 1024
#define FEATN 64
#define NCLS 5
#define EN (EE + NN)
#define INF_F __int_as_float(0x7f800000)

// ---------------- scratch (device globals; no allocs allowed) ----------------
__device__ float d_u[256];
__device__ float d_v[256];
__device__ float d_vb1[256];
__device__ float d_p[4], d_q[4], d_r[4], d_t[4];
__device__ __align__(16) float d_W2e[256 * 68];     // cols 0..63 = W2, 64 = W2@a2_src, 65 = W2@a2_dst
__device__ __align__(16) float4 d_S0[NN];
__device__ __align__(16) float4 d_S1[NN];
__device__ __align__(16) float d_g[NN * 64];        // g = h1 @ W2
__device__ float d_a2s[NN];
__device__ float d_a2d[NN];
__device__ float d_den2[NN];
__device__ __align__(16) float d_out2[NN * 64];     // gat2 numerator, then h2 in place
__device__ __align__(16) float d_pool[BB * 64];
__device__ int d_cnt[BB];
__device__ float d_fa[64];
// piecewise-linear GEMM tables: 8 (head,set) groups, 65 slots, 68 cols of (U,V)
__device__ float d_thr[8 * 64];
__device__ __align__(16) float2 d_tab[8 * 65 * 68];

// ---------------- zero scratch (fresh every replay) ----------------
__global__ void zero_k() {
    int i0 = blockIdx.x * blockDim.x + threadIdx.x;
    int stride = gridDim.x * blockDim.x;
    for (int i = i0; i < NN * 64; i += stride) d_out2[i] = 0.f;
    float* s0 = (float*)d_S0;
    float* s1 = (float*)d_S1;
    for (int i = i0; i < NN * 4; i += stride) { s0[i] = 0.f; s1[i] = 0.f; }
    for (int i = i0; i < NN; i += stride) d_den2[i] = 0.f;
    for (int i = i0; i < BB * 64; i += stride) d_pool[i] = 0.f;
    for (int i = i0; i < BB; i += stride) d_cnt[i] = 0;
    if (i0 < 64) d_fa[i0] = 0.f;
}

// ---------------- precompute rank-1 constants + extended W2 ----------------
__global__ void prep_k(const float* __restrict__ Win, const float* __restrict__ bin,
                       const float* __restrict__ W1, const float* __restrict__ a1s,
                       const float* __restrict__ a1d, const float* __restrict__ b1,
                       const float* __restrict__ W2, const float* __restrict__ a2sv,
                       const float* __restrict__ a2dv) {
    int j = threadIdx.x;  // 0..255
    float u = 0.f, v = 0.f;
    for (int k = 0; k < 64; k++) {
        float w1 = W1[k * 256 + j];
        u += Win[k] * w1;
        v += bin[k] * w1;
    }
    d_u[j] = u;
    d_v[j] = v;
    d_vb1[j] = v + b1[j];
    float as = 0.f, ad = 0.f;
    for (int c = 0; c < 64; c++) {
        float w2 = W2[j * 64 + c];
        d_W2e[j * 68 + c] = w2;
        as += w2 * a2sv[c];
        ad += w2 * a2dv[c];
    }
    d_W2e[j * 68 + 64] = as;
    d_W2e[j * 68 + 65] = ad;
    d_W2e[j * 68 + 66] = 0.f;
    d_W2e[j * 68 + 67] = 0.f;
    __syncthreads();
    if (j < 4) {
        float p = 0.f, q = 0.f, r = 0.f, t = 0.f;
        for (int c = 0; c < 64; c++) {
            int idx = j * 64 + c;
            p += d_u[idx] * a1s[idx];
            q += d_v[idx] * a1s[idx];
            r += d_u[idx] * a1d[idx];
            t += d_t[0] * 0.f + d_v[idx] * a1d[idx];
        }
        d_p[j] = p; d_q[j] = q; d_r[j] = r; d_t[j] = t;
    }
}

// ---------------- build sorted-threshold prefix/suffix tables ----------------
// block per (head, set): set 0 = u>0 (prefix over t<wh), set 1 = u<0 (suffix over t>wh)
__global__ void prep2_k() {
    int hs = blockIdx.x;
    int h = hs >> 1, set = hs & 1;
    __shared__ float W2s[64 * 68];
    __shared__ float us[64], vbs[64], key[64];
    __shared__ int sidx[64];
    __shared__ unsigned char memb[64];
    __shared__ int n_s;
    int tid = threadIdx.x;  // 128
    if (tid < 64) {
        float u = d_u[h * 64 + tid], vb = d_vb1[h * 64 + tid];
        us[tid] = u; vbs[tid] = vb;
        bool m = (set == 0) ? (u > 0.f) : (u < 0.f);
        memb[tid] = m ? 1 : 0;
        key[tid] = m ? (-vb / u) : INF_F;
    }
    for (int i = tid; i < 64 * 68; i += 128)
        W2s[i] = d_W2e[h * 64 * 68 + i];
    __syncthreads();
    if (tid < 64) {
        float ki = key[tid];
        int r = 0;
        for (int j = 0; j < 64; j++) {
            float kj = key[j];
            r += (kj < ki) || (kj == ki && j < tid);
        }
        sidx[r] = tid;
    }
    if (tid == 0) {
        int n = 0;
        for (int j = 0; j < 64; j++) n += memb[j];
        n_s = n;
    }
    __syncthreads();
    int n = n_s;
    if (tid < 64) d_thr[hs * 64 + tid] = key[sidx[tid]];   // padding slots are +INF
    if (tid < 68) {
        int c = tid;
        if (set == 0) {
            // constant base for u==0, vb>0 terms (folded into V of every pos slot)
            float base = 0.f;
            for (int j = 0; j < 64; j++)
                if (us[j] == 0.f && vbs[j] > 0.f) base += vbs[j] * W2s[j * 68 + c];
            float au = 0.f, av = base;
            d_tab[(hs * 65 + 0) * 68 + c] = make_float2(au, av);
            for (int s = 0; s < 64; s++) {
                if (s < n) {
                    int k = sidx[s];
                    au += us[k] * W2s[k * 68 + c];
                    av += vbs[k] * W2s[k * 68 + c];
                }
                d_tab[(hs * 65 + s + 1) * 68 + c] = make_float2(au, av);
            }
        } else {
            for (int s = n; s <= 64; s++)
                d_tab[(hs * 65 + s) * 68 + c] = make_float2(0.f, 0.f);
            float au = 0.f, av = 0.f;
            for (int s = n - 1; s >= 0; s--) {
                int k = sidx[s];
                au += us[k] * W2s[k * 68 + c];
                av += vbs[k] * W2s[k * 68 + c];
                d_tab[(hs * 65 + s) * 68 + c] = make_float2(au, av);
            }
        }
    }
}

// ---------------- GAT-1 edge pass: accumulate S0 and S1 ----------------
__global__ void gat1_k(const int* __restrict__ ei, const float* __restrict__ x) {
    int idx = blockIdx.x * 256 + threadIdx.x;
    if (idx >= EN) return;
    int s, d;
    if (idx < EE) { s = ei[idx]; d = ei[EE + idx]; }
    else          { s = idx - EE; d = s; }
    float xs = __ldg(&x[s]);
    float xd = __ldg(&x[d]);
    float ex[4];
#pragma unroll
    for (int h = 0; h < 4; h++) {
        float e = xs * d_p[h] + d_q[h] + xd * d_r[h] + d_t[h];
        e = (e > 0.f) ? e : 0.2f * e;
        ex[h] = expf(e);
    }
    atomicAdd(&d_S0[d], make_float4(ex[0], ex[1], ex[2], ex[3]));
    atomicAdd(&d_S1[d], make_float4(ex[0] * xs, ex[1] * xs, ex[2] * xs, ex[3] * xs));
}

// ---------------- piecewise-linear "GEMM": warp per node, ballot rank + table lookup ----------------
__global__ void g2_k() {
    __shared__ float thrS[8 * 64];
    int tid = threadIdx.x;  // 256
    for (int i = tid; i < 512; i += 256) thrS[i] = d_thr[i];
    __syncthreads();
    int lane = tid & 31, w = tid >> 5;
    int node = blockIdx.x * 8 + w;
    float4 s0 = d_S0[node], s1 = d_S1[node];
    float wh[4] = { s1.x / s0.x, s1.y / s0.y, s1.z / s0.z, s1.w / s0.w };
    float acc0 = 0.f, acc1 = 0.f, acc2 = 0.f;
#pragma unroll
    for (int hs = 0; hs < 8; hs++) {
        float wv = wh[hs >> 1];
        float t0 = thrS[hs * 64 + lane];
        float t1 = thrS[hs * 64 + 32 + lane];
        bool p0, p1;
        if ((hs & 1) == 0) { p0 = t0 < wv;  p1 = t1 < wv; }
        else               { p0 = t0 <= wv; p1 = t1 <= wv; }
        int cnt = __popc(__ballot_sync(0xffffffffu, p0)) +
                  __popc(__ballot_sync(0xffffffffu, p1));
        const float2* ptr = &d_tab[(hs * 65 + cnt) * 68];
        float2 e0 = __ldg(&ptr[lane]);
        float2 e1 = __ldg(&ptr[lane + 32]);
        acc0 += wv * e0.x + e0.y;
        acc1 += wv * e1.x + e1.y;
        if (lane < 2) {
            float2 e2 = __ldg(&ptr[64 + lane]);
            acc2 += wv * e2.x + e2.y;
        }
    }
    d_g[node * 64 + lane] = acc0;
    d_g[node * 64 + 32 + lane] = acc1;
    if (lane == 0) d_a2s[node] = acc2;
    if (lane == 1) d_a2d[node] = acc2;
}

// ---------------- GAT-2 edge pass: warp per edge, float2 lanes ----------------
__global__ void gat2_k(const int* __restrict__ ei) {
    int gid = blockIdx.x * 256 + threadIdx.x;
    int e = gid >> 5;
    int lane = gid & 31;
    if (e >= EN) return;
    int s, d;
    if (e < EE) { s = ei[e]; d = ei[EE + e]; }
    else        { s = e - EE; d = s; }
    float el = d_a2s[s] + d_a2d[d];
    el = (el > 0.f) ? el : 0.2f * el;
    float ex = expf(el);
    float2 gv = *(const float2*)&d_g[s * 64 + lane * 2];
    atomicAdd((float2*)&d_out2[d * 64 + lane * 2], make_float2(ex * gv.x, ex * gv.y));
    if (lane == 0) atomicAdd(&d_den2[d], ex);
}

// ---------------- h2 = relu(out2/den + b2), pool per graph ----------------
__global__ void hpool_k(const int* __restrict__ batch, const float* __restrict__ b2) {
    int gid = blockIdx.x * 256 + threadIdx.x;
    int n = gid >> 5;
    int lane = gid & 31;
    float inv = 1.f / d_den2[n];
    float2 o = *(float2*)&d_out2[n * 64 + lane * 2];
    float2 bb = *(const float2*)&b2[lane * 2];
    float h0 = fmaxf(o.x * inv + bb.x, 0.f);
    float h1 = fmaxf(o.y * inv + bb.y, 0.f);
    *(float2*)&d_out2[n * 64 + lane * 2] = make_float2(h0, h1);
    int bg = batch[n];
    atomicAdd((float2*)&d_pool[bg * 64 + lane * 2], make_float2(h0, h1));
    if (lane == 0) atomicAdd(&d_cnt[bg], 1);
}

// ---------------- feature attention: per-node 64x64 matvec + sigmoid ----------------
__global__ void att_k(const float* __restrict__ faW1, const float* __restrict__ fab1,
                      const float* __restrict__ faW2, const float* __restrict__ fab2,
                      const int* __restrict__ batch) {
    __shared__ __align__(16) float W1s[64 * 64];
    __shared__ __align__(16) float b1s[64];
    __shared__ __align__(16) float w2s[64];
    __shared__ float fas[64];
    int tid = threadIdx.x;  // 128
    for (int i = tid; i < 4096; i += 128) W1s[i] = faW1[i];
    if (tid < 64) { b1s[tid] = fab1[tid]; w2s[tid] = faW2[tid]; fas[tid] = 0.f; }
    __syncthreads();
    int n = blockIdx.x * 128 + tid;
    float hrow[64];
#pragma unroll
    for (int i = 0; i < 16; i++) {
        float4 v = *(const float4*)&d_out2[n * 64 + i * 4];
        hrow[i * 4] = v.x; hrow[i * 4 + 1] = v.y;
        hrow[i * 4 + 2] = v.z; hrow[i * 4 + 3] = v.w;
    }
    float res = fab2[0];
#pragma unroll
    for (int tc = 0; tc < 4; tc++) {
        float4 acc[4];
#pragma unroll
        for (int i = 0; i < 4; i++) acc[i] = *(const float4*)&b1s[tc * 16 + i * 4];
#pragma unroll
        for (int c = 0; c < 64; c++) {
            float hc = hrow[c];
#pragma unroll
            for (int i = 0; i < 4; i++) {
                float4 wv = *(const float4*)&W1s[c * 64 + tc * 16 + i * 4];
                acc[i].x += hc * wv.x; acc[i].y += hc * wv.y;
                acc[i].z += hc * wv.z; acc[i].w += hc * wv.w;
            }
        }
#pragma unroll
        for (int i = 0; i < 4; i++) {
            float4 wv2 = *(const float4*)&w2s[tc * 16 + i * 4];
            res += fmaxf(acc[i].x, 0.f) * wv2.x + fmaxf(acc[i].y, 0.f) * wv2.y +
                   fmaxf(acc[i].z, 0.f) * wv2.z + fmaxf(acc[i].w, 0.f) * wv2.w;
        }
    }
    float att = 1.f / (1.f + expf(-res));
    int f = n - batch[n] * FEATN;
    atomicAdd(&fas[f], att);
    __syncthreads();
    if (tid < 64) atomicAdd(&d_fa[tid], fas[tid]);
}

// ---------------- classifier + final_attention ----------------
__global__ void fin_k(const float* __restrict__ clsW, const float* __restrict__ clsb,
                      float* __restrict__ out) {
    if (blockIdx.x < 4) {
        int b = blockIdx.x * 256 + threadIdx.x;
        float inv = 1.f / fmaxf((float)d_cnt[b], 1.f);
        float p[64];
#pragma unroll
        for (int i = 0; i < 16; i++) {
            float4 v = *(const float4*)&d_pool[b * 64 + i * 4];
            p[i * 4] = v.x * inv; p[i * 4 + 1] = v.y * inv;
            p[i * 4 + 2] = v.z * inv; p[i * 4 + 3] = v.w * inv;
        }
#pragma unroll
        for (int j = 0; j < NCLS; j++) {
            float o = clsb[j];
#pragma unroll
            for (int c = 0; c < 64; c++) o += p[c] * clsW[c * NCLS + j];
            out[b * NCLS + j] = o;
        }
    } else {
        int f = threadIdx.x;
        if (f < 64) out[BB * NCLS + f] = d_fa[f] * (1.f / (float)BB);
    }
}

extern "C" void kernel_launch(void* const* d_in, const int* in_sizes, int n_in,
                              void* d_out, int out_size) {
    const float* x    = (const float*)d_in[0];
    const int*   ei   = (const int*)d_in[1];
    const int*   bat  = (const int*)d_in[2];
    const float* Win  = (const float*)d_in[3];
    const float* bin  = (const float*)d_in[4];
    const float* W1   = (const float*)d_in[5];
    const float* a1s  = (const float*)d_in[6];
    const float* a1d  = (const float*)d_in[7];
    const float* b1   = (const float*)d_in[8];
    const float* W2   = (const float*)d_in[9];
    const float* a2s  = (const float*)d_in[10];
    const float* a2d  = (const float*)d_in[11];
    const float* b2   = (const float*)d_in[12];
    const float* faW1 = (const float*)d_in[13];
    const float* fab1 = (const float*)d_in[14];
    const float* faW2 = (const float*)d_in[15];
    const float* fab2 = (const float*)d_in[16];
    const float* clsW = (const float*)d_in[17];
    const float* clsb = (const float*)d_in[18];
    float* out = (float*)d_out;

    zero_k<<<1024, 256>>>();
    prep_k<<<1, 256>>>(Win, bin, W1, a1s, a1d, b1, W2, a2s, a2d);
    prep2_k<<<8, 128>>>();
    gat1_k<<<(EN + 255) / 256, 256>>>(ei, x);
    g2_k<<<NN / 8, 256>>>();
    gat2_k<<<EN / 8, 256>>>(ei);
    hpool_k<<<NN / 8, 256>>>(bat, b2);
    att_k<<<NN / 128, 128>>>(faW1, fab1, faW2, fab2, bat);
    fin_k<<<5, 256>>>(clsW, clsb, out);
}